// round 15
// baseline (speedup 1.0000x reference)
#include <cuda_runtime.h>
#include <cuda_fp16.h>
#include <cstdint>
#include <math.h>

namespace {
constexpr int Tn  = 4096;
constexpr int Hd  = 1024;
constexpr int Fd  = 4096;
constexpr int F2d = 2048;
constexpr int Ex  = 8;
constexpr int STAGES = 4;
constexpr int ASTW = 64 * 20;           // A stage words [64 m][20] (32 halfs K + pad)
constexpr int BSTW = 32 * 68;           // B stage words [32 k][68] (128 halfs N + pad)
constexpr int STW  = ASTW + BSTW;       // 3456 words
constexpr int SMEM_BYTES = STAGES * STW * 4 + 256;
}
static constexpr size_t SZF = (size_t)Tn * Fd;
static constexpr size_t SZT = (size_t)Tn * F2d;
static constexpr size_t SZD = (size_t)Tn * Hd;

// ----------------- device scratch (referenced ONLY in device code) --------
__device__ __half g_nx[(size_t)Tn * Hd];
__device__ __half g_h1[(size_t)Ex * Tn * Fd];
__device__ __half g_h2[(size_t)Ex * Tn * Fd];
__device__ __half g_t1[(size_t)2 * Tn * F2d];
__device__ float  g_dn[(size_t)Ex * Tn * Hd];
__device__ float  g_w2[Tn * 2];
__device__ int    g_list[Ex * Tn];
__device__ int    g_cnt[Ex];
__device__ int    g_te[Tn * 2];
__device__ int    g_tp[Tn * 2];
// fp16 weights, same [K][N] layout as inputs
__device__ __half g_upW16 [(size_t)Ex * Hd * Fd];
__device__ __half g_dnW16 [(size_t)Ex * Fd * Hd];
__device__ __half g_s0W16 [(size_t)2 * Fd * Fd];
__device__ __half g_s1aW16[(size_t)2 * Fd * F2d];
__device__ __half g_s1bW16[(size_t)2 * F2d * Fd];
__device__ __half g_s2W16 [(size_t)2 * Fd * Fd];

__device__ __forceinline__ float gelu_f(float v) {
    return 0.5f * v * (1.0f + erff(v * 0.70710678118654752f));
}
__device__ __forceinline__ void cpa16(uint32_t dst, const void* src, bool pred) {
    int sz = pred ? 16 : 0;
    asm volatile("cp.async.cg.shared.global [%0], [%1], 16, %2;\n"
                 :: "r"(dst), "l"(src), "r"(sz));
}

__global__ void zero_cnt_kernel() { if (threadIdx.x < Ex) g_cnt[threadIdx.x] = 0; }

// ------------- streaming fp32 -> fp16 convert; dest symbol by template ----
template <int J>
__global__ __launch_bounds__(256, 1) void conv16_kernel(const float* __restrict__ W)
{
    __half* O = (J == 0) ? g_upW16 : (J == 1) ? g_dnW16 : (J == 2) ? g_s0W16
              : (J == 3) ? g_s1aW16 : (J == 4) ? g_s1bW16 : g_s2W16;
    size_t i = ((size_t)blockIdx.x * 256 + threadIdx.x) * 8;
    float4 a = *reinterpret_cast<const float4*>(W + i);
    float4 b = *reinterpret_cast<const float4*>(W + i + 4);
    __half2 h[4];
    h[0] = __floats2half2_rn(a.x, a.y); h[1] = __floats2half2_rn(a.z, a.w);
    h[2] = __floats2half2_rn(b.x, b.y); h[3] = __floats2half2_rn(b.z, b.w);
    *reinterpret_cast<uint4*>(O + i) = *reinterpret_cast<uint4*>(h);
}

// --------------- fused LN + router + scatter (fp16 nx out) ----------------
__global__ __launch_bounds__(256, 1) void ln_router_kernel(
    const float* __restrict__ x, const float* __restrict__ lng,
    const float* __restrict__ lnb, const float* __restrict__ rw)
{
    int t = blockIdx.x, tid = threadIdx.x, lane = tid & 31, wid = tid >> 5;
    __shared__ float ss[8], sq[8], sl[8][8], slog[8];
    float4 v = reinterpret_cast<const float4*>(x + (size_t)t * Hd)[tid];
    float s = v.x + v.y + v.z + v.w;
    float q = v.x * v.x + v.y * v.y + v.z * v.z + v.w * v.w;
    #pragma unroll
    for (int o = 16; o; o >>= 1) { s += __shfl_xor_sync(~0u, s, o); q += __shfl_xor_sync(~0u, q, o); }
    if (lane == 0) { ss[wid] = s; sq[wid] = q; }
    __syncthreads();
    if (tid == 0) {
        float S = 0.f, Q = 0.f;
        for (int i = 0; i < 8; i++) { S += ss[i]; Q += sq[i]; }
        ss[0] = S; sq[0] = Q;
    }
    __syncthreads();
    float mean = ss[0] * (1.0f / Hd);
    float var = fmaxf(sq[0] * (1.0f / Hd) - mean * mean, 0.0f);
    float rs = rsqrtf(var + 1e-5f);
    float4 g4 = reinterpret_cast<const float4*>(lng)[tid];
    float4 b4 = reinterpret_cast<const float4*>(lnb)[tid];
    float n0v = (v.x - mean) * rs * g4.x + b4.x;
    float n1v = (v.y - mean) * rs * g4.y + b4.y;
    float n2v = (v.z - mean) * rs * g4.z + b4.z;
    float n3v = (v.w - mean) * rs * g4.w + b4.w;
    __half2* nh = reinterpret_cast<__half2*>(g_nx + (size_t)t * Hd);
    nh[tid * 2] = __floats2half2_rn(n0v, n1v);
    nh[tid * 2 + 1] = __floats2half2_rn(n2v, n3v);

    float nv[4] = {n0v, n1v, n2v, n3v};
    float acc[8] = {0.f,0.f,0.f,0.f,0.f,0.f,0.f,0.f};
    int i0 = tid * 4;
    #pragma unroll
    for (int j = 0; j < 4; j++) {
        const float4* rr = reinterpret_cast<const float4*>(rw + (size_t)(i0 + j) * Ex);
        float4 r0 = rr[0], r1 = rr[1];
        acc[0] += nv[j] * r0.x; acc[1] += nv[j] * r0.y;
        acc[2] += nv[j] * r0.z; acc[3] += nv[j] * r0.w;
        acc[4] += nv[j] * r1.x; acc[5] += nv[j] * r1.y;
        acc[6] += nv[j] * r1.z; acc[7] += nv[j] * r1.w;
    }
    #pragma unroll
    for (int e = 0; e < 8; e++)
        #pragma unroll
        for (int o = 16; o; o >>= 1) acc[e] += __shfl_xor_sync(~0u, acc[e], o);
    if (lane == 0)
        #pragma unroll
        for (int e = 0; e < 8; e++) sl[wid][e] = acc[e];
    __syncthreads();
    if (tid < 8) {
        float L = 0.f;
        for (int w = 0; w < 8; w++) L += sl[w][tid];
        slog[tid] = L;
    }
    __syncthreads();
    if (tid == 0) {
        float p[8], mx = slog[0];
        for (int e = 1; e < 8; e++) mx = fmaxf(mx, slog[e]);
        float Z = 0.f;
        for (int e = 0; e < 8; e++) { p[e] = expf(slog[e] - mx); Z += p[e]; }
        float iZ = 1.0f / Z;
        for (int e = 0; e < 8; e++) p[e] *= iZ;
        int i1 = 0;
        for (int e = 1; e < 8; e++) if (p[e] > p[i1]) i1 = e;
        int i2 = (i1 == 0) ? 1 : 0;
        for (int e = 0; e < 8; e++) if (e != i1 && p[e] > p[i2]) i2 = e;
        float iw = 1.0f / (p[i1] + p[i2]);
        g_w2[2*t] = p[i1] * iw; g_w2[2*t+1] = p[i2] * iw;
        int p1 = atomicAdd(&g_cnt[i1], 1); g_list[i1 * Tn + p1] = t;
        int p2 = atomicAdd(&g_cnt[i2], 1); g_list[i2 * Tn + p2] = t;
        g_te[2*t] = i1; g_te[2*t+1] = i2;
        g_tp[2*t] = p1; g_tp[2*t+1] = p2;
    }
}

// -- fp16 m16n8k16 GEMM: 64m x 128n, 4 warps, 4-stage (K32), 4 CTAs/SM ----
enum { M_UP = 0, M_S0, M_S1A, M_S1B, M_S2, M_DOWN };

template <int MODE>
__global__ __launch_bounds__(128, 4) void gemm16_kernel(const float* __restrict__ biasb)
{
    constexpr bool GATHER  = (MODE == M_UP);
    constexpr bool DO_GELU = (MODE == M_UP || MODE == M_S1A || MODE == M_S2);
    constexpr bool OUT_F32 = (MODE == M_DOWN);
    constexpr int  e0    = (MODE == M_S1A || MODE == M_S1B) ? 1 : (MODE == M_S2 ? 2 : 0);
    constexpr int  estep = (MODE == M_UP || MODE == M_DOWN) ? 1 : 4;
    constexpr int  Kd    = (MODE == M_UP) ? Hd : (MODE == M_S1B ? F2d : Fd);
    constexpr int  Nf    = (MODE == M_S1A) ? F2d : (MODE == M_DOWN ? Hd : Fd);
    constexpr int  KT    = Kd / 32;

    int z = blockIdx.z, e = e0 + estep * z;
    int M = g_cnt[e];
    int m0 = blockIdx.y * 64;
    if (m0 >= M) return;
    int n0 = blockIdx.x * 128;

    const __half* Wt =
        (MODE == M_UP)  ? g_upW16  : (MODE == M_S0)  ? g_s0W16  :
        (MODE == M_S1A) ? g_s1aW16 : (MODE == M_S1B) ? g_s1bW16 :
        (MODE == M_S2)  ? g_s2W16  : g_dnW16;

    const __half* A; void* Cv; int ldc;
    if constexpr (MODE == M_UP)       { A = g_nx;                   Cv = g_h1 + (size_t)e * SZF; ldc = Fd;  }
    else if constexpr (MODE == M_S0)  { A = g_h1 + (size_t)e * SZF; Cv = g_h2 + (size_t)e * SZF; ldc = Fd;  }
    else if constexpr (MODE == M_S1A) { A = g_h1 + (size_t)e * SZF; Cv = g_t1 + (size_t)z * SZT; ldc = F2d; }
    else if constexpr (MODE == M_S1B) { A = g_t1 + (size_t)z * SZT; Cv = g_h2 + (size_t)e * SZF; ldc = Fd;  }
    else if constexpr (MODE == M_S2)  { A = g_h1 + (size_t)e * SZF; Cv = g_h2 + (size_t)e * SZF; ldc = Fd;  }
    else { A = (((e & 3) == 3) ? g_h1 : g_h2) + (size_t)e * SZF;    Cv = g_dn + (size_t)e * SZD; ldc = Hd;  }

    const __half* Bp = Wt + (size_t)z * Kd * Nf + n0;   // [Kd][Nf] k-major
    const float*  bp = biasb + (size_t)z * Nf + n0;

    extern __shared__ uint32_t smem[];
    int* srow = (int*)(smem + STAGES * STW);
    int tid = threadIdx.x, lane = tid & 31, wid = tid >> 5;

    if (GATHER) {
        if (tid < 64) {
            int r = m0 + tid;
            srow[tid] = (r < M) ? g_list[e * Tn + r] : 0;
        }
        __syncthreads();
    }

    // A copy: m-row = (tid>>2)+32i (i<2), chunk = (tid&3) (4 x 16B per row)
    int ar = tid >> 2;
    int ac = (tid & 3) * 4;            // words; halfs = ac*2
    // B copy: k-row = (tid>>4)+8i (i<4), chunk = (tid&15) (16 x 16B per row)
    int brw = tid >> 4;
    int bcl = (tid & 15) * 4;

    const __half* acur[2]; bool aval[2];
    #pragma unroll
    for (int i = 0; i < 2; i++) {
        int r = m0 + ar + 32 * i;
        aval[i] = (r < M);
        int src = GATHER ? (aval[i] ? srow[ar + 32 * i] : 0) : (aval[i] ? r : 0);
        acur[i] = A + (size_t)src * Kd + ac * 2;
    }
    const __half* bcur[4];
    #pragma unroll
    for (int i = 0; i < 4; i++)
        bcur[i] = Bp + (size_t)(brw + 8 * i) * Nf + bcl * 2;

    uint32_t sbase;
    { asm("{ .reg .u64 t; cvta.to.shared.u64 t, %1; cvt.u32.u64 %0, t; }"
          : "=r"(sbase) : "l"(smem)); }

    auto issue = [&](int kt) {
        if (kt < KT) {
            int st = kt & 3;
            uint32_t abase = sbase + (uint32_t)(st * STW) * 4;
            uint32_t bbase = abase + (uint32_t)ASTW * 4;
            int ko = kt * 32;   // halfs
            #pragma unroll
            for (int i = 0; i < 2; i++)
                cpa16(abase + (uint32_t)((ar + 32 * i) * 20 + ac) * 4, acur[i] + ko, aval[i]);
            #pragma unroll
            for (int i = 0; i < 4; i++)
                cpa16(bbase + (uint32_t)((brw + 8 * i) * 68 + bcl) * 4,
                      bcur[i] + (size_t)ko * Nf, true);
        }
        asm volatile("cp.async.commit_group;\n" ::: "memory");
    };
    issue(0); issue(1); issue(2);

    int wm = wid & 1, wn = wid >> 1;   // 2x2 warps, warp tile 32m x 64n
    int qq = lane & 3, lg = lane >> 2;
    // B ldmatrix.trans lane addressing
    int krl = (lane & 7) + ((lane >> 3) & 1) * 8;
    int ncl = (lane >> 4) * 8;
    // A ldmatrix lane addressing: row = rm + (lane&15), kbyte = (lane>>4)*16
    uint32_t aoff[2];
    #pragma unroll
    for (int mi = 0; mi < 2; mi++) {
        int rm = wm * 32 + mi * 16 + (lane & 15);
        aoff[mi] = (uint32_t)rm * 80 + (uint32_t)(lane >> 4) * 16;
    }

    float acc[2][8][4];
    #pragma unroll
    for (int a = 0; a < 2; a++)
        #pragma unroll
        for (int b = 0; b < 8; b++)
            #pragma unroll
            for (int c = 0; c < 4; c++) acc[a][b][c] = 0.f;

    for (int kt = 0; kt < KT; kt++) {
        int st = kt & 3;
        asm volatile("cp.async.wait_group 2;\n" ::: "memory");
        __syncthreads();

        uint32_t Ab = sbase + (uint32_t)(st * STW) * 4;
        uint32_t Bb = Ab + (uint32_t)ASTW * 4;
        uint32_t bl = Bb + (uint32_t)krl * 272 + (uint32_t)(wn * 64 + ncl) * 2;
        #pragma unroll
        for (int kk = 0; kk < 2; kk++) {
            uint32_t af[2][4];
            #pragma unroll
            for (int mi = 0; mi < 2; mi++) {
                uint32_t addr = Ab + aoff[mi] + (uint32_t)(kk * 32);
                asm volatile(
                    "ldmatrix.sync.aligned.m8n8.x4.shared.b16 {%0,%1,%2,%3}, [%4];"
                    : "=r"(af[mi][0]), "=r"(af[mi][1]), "=r"(af[mi][2]), "=r"(af[mi][3])
                    : "r"(addr));
            }
            uint32_t bf[8][2];
            #pragma unroll
            for (int nj = 0; nj < 4; nj++) {
                uint32_t addr = bl + (uint32_t)(kk * 16) * 272 + (uint32_t)nj * 32;
                asm volatile(
                    "ldmatrix.sync.aligned.m8n8.x4.trans.shared.b16 {%0,%1,%2,%3}, [%4];"
                    : "=r"(bf[2*nj][0]), "=r"(bf[2*nj][1]),
                      "=r"(bf[2*nj+1][0]), "=r"(bf[2*nj+1][1])
                    : "r"(addr));
            }
            #pragma unroll
            for (int mi = 0; mi < 2; mi++)
                #pragma unroll
                for (int ni = 0; ni < 8; ni++)
                    asm volatile(
                        "mma.sync.aligned.m16n8k16.row.col.f32.f16.f16.f32 "
                        "{%0,%1,%2,%3}, {%4,%5,%6,%7}, {%8,%9}, {%0,%1,%2,%3};\n"
                        : "+f"(acc[mi][ni][0]), "+f"(acc[mi][ni][1]),
                          "+f"(acc[mi][ni][2]), "+f"(acc[mi][ni][3])
                        : "r"(af[mi][0]), "r"(af[mi][1]), "r"(af[mi][2]), "r"(af[mi][3]),
                          "r"(bf[ni][0]), "r"(bf[ni][1]));
        }
        issue(kt + 3);
    }

    #pragma unroll
    for (int mi = 0; mi < 2; mi++) {
        #pragma unroll
        for (int hf = 0; hf < 2; hf++) {
            int r = m0 + wm * 32 + mi * 16 + lg + hf * 8;
            if (r < M) {
                #pragma unroll
                for (int ni = 0; ni < 8; ni++) {
                    int c = wn * 64 + ni * 8 + 2 * qq;
                    float v0 = acc[mi][ni][hf * 2 + 0] + bp[c];
                    float v1 = acc[mi][ni][hf * 2 + 1] + bp[c + 1];
                    if (DO_GELU) { v0 = gelu_f(v0); v1 = gelu_f(v1); }
                    if (OUT_F32) {
                        float* crow = (float*)Cv + (size_t)r * ldc + n0;
                        *reinterpret_cast<float2*>(crow + c) = make_float2(v0, v1);
                    } else {
                        __half* crow = (__half*)Cv + (size_t)r * ldc + n0;
                        *reinterpret_cast<__half2*>(crow + c) = __floats2half2_rn(v0, v1);
                    }
                }
            }
        }
    }
}

// ---------------- row LayerNorm over F on fp16 (optional gelu) ------------
template <bool DO_GELU>
__global__ __launch_bounds__(256, 1) void rowln16_kernel(
    int e0, const float* __restrict__ gg, const float* __restrict__ bb)
{
    int z = blockIdx.y, e = e0 + 4 * z;
    int row = blockIdx.x;
    if (row >= g_cnt[e]) return;
    __half* p = g_h2 + (size_t)e * SZF + (size_t)row * Fd;
    int tid = threadIdx.x, lane = tid & 31, wid = tid >> 5;
    __shared__ float ss[8], sq[8];
    uint4* p4 = reinterpret_cast<uint4*>(p);
    uint4 u[2];
    float vals[16];
    float s = 0.f, q = 0.f;
    #pragma unroll
    for (int i = 0; i < 2; i++) {
        u[i] = p4[tid + 256 * i];
        const __half2* h2 = reinterpret_cast<const __half2*>(&u[i]);
        #pragma unroll
        for (int j = 0; j < 4; j++) {
            float2 f = __half22float2(h2[j]);
            vals[i * 8 + 2 * j] = f.x; vals[i * 8 + 2 * j + 1] = f.y;
            s += f.x + f.y; q += f.x * f.x + f.y * f.y;
        }
    }
    #pragma unroll
    for (int o = 16; o; o >>= 1) { s += __shfl_xor_sync(~0u, s, o); q += __shfl_xor_sync(~0u, q, o); }
    if (lane == 0) { ss[wid] = s; sq[wid] = q; }
    __syncthreads();
    if (tid == 0) {
        float S = 0.f, Q = 0.f;
        for (int i = 0; i < 8; i++) { S += ss[i]; Q += sq[i]; }
        ss[0] = S; sq[0] = Q;
    }
    __syncthreads();
    float mean = ss[0] * (1.0f / Fd);
    float var = fmaxf(sq[0] * (1.0f / Fd) - mean * mean, 0.0f);
    float rs = rsqrtf(var + 1e-5f);
    const float* gr = gg + (size_t)z * Fd;
    const float* br = bb + (size_t)z * Fd;
    #pragma unroll
    for (int i = 0; i < 2; i++) {
        __half2 out[4];
        #pragma unroll
        for (int j = 0; j < 4; j++) {
            int idx = (tid + 256 * i) * 8 + 2 * j;
            float o0 = (vals[i * 8 + 2 * j]     - mean) * rs * gr[idx]     + br[idx];
            float o1 = (vals[i * 8 + 2 * j + 1] - mean) * rs * gr[idx + 1] + br[idx + 1];
            if (DO_GELU) { o0 = gelu_f(o0); o1 = gelu_f(o1); }
            out[j] = __floats2half2_rn(o0, o1);
        }
        p4[tid + 256 * i] = *reinterpret_cast<uint4*>(out);
    }
}

// ------------------------- combine epilogue -------------------------------
__global__ __launch_bounds__(256, 1) void combine_kernel(
    const float* __restrict__ x, float* __restrict__ y)
{
    int t = blockIdx.x, tid = threadIdx.x;
    int e1 = g_te[2*t], e2 = g_te[2*t+1];
    int p1 = g_tp[2*t], p2 = g_tp[2*t+1];
    float w1 = g_w2[2*t], w2 = g_w2[2*t+1];
    const float4* xv = reinterpret_cast<const float4*>(x + (size_t)t * Hd);
    const float4* d1 = reinterpret_cast<const float4*>(g_dn + (size_t)e1 * SZD + (size_t)p1 * Hd);
    const float4* d2 = reinterpret_cast<const float4*>(g_dn + (size_t)e2 * SZD + (size_t)p2 * Hd);
    float4 a = xv[tid], b = d1[tid], c = d2[tid], o;
    o.x = a.x + w1 * b.x + w2 * c.x;
    o.y = a.y + w1 * b.y + w2 * c.y;
    o.z = a.z + w1 * b.z + w2 * c.z;
    o.w = a.w + w1 * b.w + w2 * c.w;
    reinterpret_cast<float4*>(y + (size_t)t * Hd)[tid] = o;
}

// ---------------------------------------------------------------------------
extern "C" void kernel_launch(void* const* d_in, const int* in_sizes, int n_in,
                              void* d_out, int out_size)
{
    const float* x        = (const float*)d_in[0];
    const float* ln_g     = (const float*)d_in[1];
    const float* ln_b     = (const float*)d_in[2];
    const float* router_w = (const float*)d_in[3];
    const float* up_W     = (const float*)d_in[4];
    const float* up_b     = (const float*)d_in[5];
    const float* down_W   = (const float*)d_in[6];
    const float* down_b   = (const float*)d_in[7];
    const float* spec0_W  = (const float*)d_in[8];
    const float* spec0_b  = (const float*)d_in[9];
    const float* ln0_g    = (const float*)d_in[10];
    const float* ln0_b    = (const float*)d_in[11];
    const float* spec1a_W = (const float*)d_in[12];
    const float* spec1a_b = (const float*)d_in[13];
    const float* spec1b_W = (const float*)d_in[14];
    const float* spec1b_b = (const float*)d_in[15];
    const float* ln1_g    = (const float*)d_in[16];
    const float* ln1_b    = (const float*)d_in[17];
    const float* spec2_W  = (const float*)d_in[18];
    const float* spec2_b  = (const float*)d_in[19];
    float* y = (float*)d_out;

    static bool attr_done = false;
    if (!attr_done) {
        cudaFuncSetAttribute((const void*)gemm16_kernel<M_UP>,   cudaFuncAttributeMaxDynamicSharedMemorySize, SMEM_BYTES);
        cudaFuncSetAttribute((const void*)gemm16_kernel<M_S0>,   cudaFuncAttributeMaxDynamicSharedMemorySize, SMEM_BYTES);
        cudaFuncSetAttribute((const void*)gemm16_kernel<M_S1A>,  cudaFuncAttributeMaxDynamicSharedMemorySize, SMEM_BYTES);
        cudaFuncSetAttribute((const void*)gemm16_kernel<M_S1B>,  cudaFuncAttributeMaxDynamicSharedMemorySize, SMEM_BYTES);
        cudaFuncSetAttribute((const void*)gemm16_kernel<M_S2>,   cudaFuncAttributeMaxDynamicSharedMemorySize, SMEM_BYTES);
        cudaFuncSetAttribute((const void*)gemm16_kernel<M_DOWN>, cudaFuncAttributeMaxDynamicSharedMemorySize, SMEM_BYTES);
        attr_done = true;
    }

    conv16_kernel<0><<<(int)((size_t)Ex * Hd * Fd / 2048), 256>>>(up_W);       // 0
    zero_cnt_kernel<<<1, 32>>>();                                              // 1
    ln_router_kernel<<<Tn, 256>>>(x, ln_g, ln_b, router_w);                    // 2
    conv16_kernel<2><<<(int)((size_t)2 * Fd * Fd / 2048),  256>>>(spec0_W);    // 3
    conv16_kernel<1><<<(int)((size_t)Ex * Fd * Hd / 2048), 256>>>(down_W);     // 4

    gemm16_kernel<M_UP><<<dim3(Fd/128, Tn/64, 8), 128, SMEM_BYTES>>>(up_b);    // 5 <- profiled

    conv16_kernel<3><<<(int)((size_t)2 * Fd * F2d / 2048), 256>>>(spec1a_W);
    conv16_kernel<5><<<(int)((size_t)2 * Fd * Fd / 2048),  256>>>(spec2_W);

    gemm16_kernel<M_S0> <<<dim3(Fd/128,  Tn/64, 2), 128, SMEM_BYTES>>>(spec0_b);
    gemm16_kernel<M_S1A><<<dim3(F2d/128, Tn/64, 2), 128, SMEM_BYTES>>>(spec1a_b);
    gemm16_kernel<M_S2> <<<dim3(Fd/128,  Tn/64, 2), 128, SMEM_BYTES>>>(spec2_b);

    rowln16_kernel<true><<<dim3(Tn, 2), 256>>>(0, ln0_g, ln0_b);
    conv16_kernel<4><<<(int)((size_t)2 * F2d * Fd / 2048), 256>>>(spec1b_W);

    gemm16_kernel<M_S1B><<<dim3(Fd/128, Tn/64, 2), 128, SMEM_BYTES>>>(spec1b_b);
    rowln16_kernel<false><<<dim3(Tn, 2), 256>>>(1, ln1_g, ln1_b);

    gemm16_kernel<M_DOWN><<<dim3(Hd/128, Tn/64, 8), 128, SMEM_BYTES>>>(down_b);

    combine_kernel<<<Tn, 256>>>(x, y);
}

// round 16
// speedup vs baseline: 1.0665x; 1.0665x over previous
#include <cuda_runtime.h>
#include <cuda_fp16.h>
#include <cstdint>
#include <math.h>

namespace {
constexpr int Tn  = 4096;
constexpr int Hd  = 1024;
constexpr int Fd  = 4096;
constexpr int F2d = 2048;
constexpr int Ex  = 8;
constexpr int STAGES = 2;
constexpr int ASTW = 64 * 36;           // A stage words [64 m][36] (64 halfs K + pad)
constexpr int BSTW = 64 * 68;           // B stage words [64 k][68] (128 halfs N + pad)
constexpr int STW  = ASTW + BSTW;       // 6656 words
constexpr int SMEM_BYTES = STAGES * STW * 4 + 256;
}
static constexpr size_t SZF = (size_t)Tn * Fd;
static constexpr size_t SZT = (size_t)Tn * F2d;
static constexpr size_t SZD = (size_t)Tn * Hd;

// ----------------- device scratch (referenced ONLY in device code) --------
__device__ __half g_nx[(size_t)Tn * Hd];
__device__ __half g_h1[(size_t)Ex * Tn * Fd];
__device__ __half g_h2[(size_t)Ex * Tn * Fd];
__device__ __half g_t1[(size_t)2 * Tn * F2d];
__device__ float  g_dn[(size_t)Ex * Tn * Hd];
__device__ float  g_w2[Tn * 2];
__device__ int    g_list[Ex * Tn];
__device__ int    g_cnt[Ex];
__device__ int    g_te[Tn * 2];
__device__ int    g_tp[Tn * 2];
// fp16 weights, same [K][N] layout as inputs
__device__ __half g_upW16 [(size_t)Ex * Hd * Fd];
__device__ __half g_dnW16 [(size_t)Ex * Fd * Hd];
__device__ __half g_s0W16 [(size_t)2 * Fd * Fd];
__device__ __half g_s1aW16[(size_t)2 * Fd * F2d];
__device__ __half g_s1bW16[(size_t)2 * F2d * Fd];
__device__ __half g_s2W16 [(size_t)2 * Fd * Fd];

__device__ __forceinline__ float gelu_f(float v) {
    return 0.5f * v * (1.0f + erff(v * 0.70710678118654752f));
}
__device__ __forceinline__ void cpa16(uint32_t dst, const void* src, bool pred) {
    int sz = pred ? 16 : 0;
    asm volatile("cp.async.cg.shared.global [%0], [%1], 16, %2;\n"
                 :: "r"(dst), "l"(src), "r"(sz));
}

__global__ void zero_cnt_kernel() { if (threadIdx.x < Ex) g_cnt[threadIdx.x] = 0; }

// ------------- streaming fp32 -> fp16 convert; dest symbol by template ----
template <int J>
__global__ __launch_bounds__(256, 1) void conv16_kernel(const float* __restrict__ W)
{
    __half* O = (J == 0) ? g_upW16 : (J == 1) ? g_dnW16 : (J == 2) ? g_s0W16
              : (J == 3) ? g_s1aW16 : (J == 4) ? g_s1bW16 : g_s2W16;
    size_t i = ((size_t)blockIdx.x * 256 + threadIdx.x) * 8;
    float4 a = *reinterpret_cast<const float4*>(W + i);
    float4 b = *reinterpret_cast<const float4*>(W + i + 4);
    __half2 h[4];
    h[0] = __floats2half2_rn(a.x, a.y); h[1] = __floats2half2_rn(a.z, a.w);
    h[2] = __floats2half2_rn(b.x, b.y); h[3] = __floats2half2_rn(b.z, b.w);
    *reinterpret_cast<uint4*>(O + i) = *reinterpret_cast<uint4*>(h);
}

// --------------- fused LN + router + scatter (fp16 nx out) ----------------
__global__ __launch_bounds__(256, 1) void ln_router_kernel(
    const float* __restrict__ x, const float* __restrict__ lng,
    const float* __restrict__ lnb, const float* __restrict__ rw)
{
    int t = blockIdx.x, tid = threadIdx.x, lane = tid & 31, wid = tid >> 5;
    __shared__ float ss[8], sq[8], sl[8][8], slog[8];
    float4 v = reinterpret_cast<const float4*>(x + (size_t)t * Hd)[tid];
    float s = v.x + v.y + v.z + v.w;
    float q = v.x * v.x + v.y * v.y + v.z * v.z + v.w * v.w;
    #pragma unroll
    for (int o = 16; o; o >>= 1) { s += __shfl_xor_sync(~0u, s, o); q += __shfl_xor_sync(~0u, q, o); }
    if (lane == 0) { ss[wid] = s; sq[wid] = q; }
    __syncthreads();
    if (tid == 0) {
        float S = 0.f, Q = 0.f;
        for (int i = 0; i < 8; i++) { S += ss[i]; Q += sq[i]; }
        ss[0] = S; sq[0] = Q;
    }
    __syncthreads();
    float mean = ss[0] * (1.0f / Hd);
    float var = fmaxf(sq[0] * (1.0f / Hd) - mean * mean, 0.0f);
    float rs = rsqrtf(var + 1e-5f);
    float4 g4 = reinterpret_cast<const float4*>(lng)[tid];
    float4 b4 = reinterpret_cast<const float4*>(lnb)[tid];
    float n0v = (v.x - mean) * rs * g4.x + b4.x;
    float n1v = (v.y - mean) * rs * g4.y + b4.y;
    float n2v = (v.z - mean) * rs * g4.z + b4.z;
    float n3v = (v.w - mean) * rs * g4.w + b4.w;
    __half2* nh = reinterpret_cast<__half2*>(g_nx + (size_t)t * Hd);
    nh[tid * 2] = __floats2half2_rn(n0v, n1v);
    nh[tid * 2 + 1] = __floats2half2_rn(n2v, n3v);

    float nv[4] = {n0v, n1v, n2v, n3v};
    float acc[8] = {0.f,0.f,0.f,0.f,0.f,0.f,0.f,0.f};
    int i0 = tid * 4;
    #pragma unroll
    for (int j = 0; j < 4; j++) {
        const float4* rr = reinterpret_cast<const float4*>(rw + (size_t)(i0 + j) * Ex);
        float4 r0 = rr[0], r1 = rr[1];
        acc[0] += nv[j] * r0.x; acc[1] += nv[j] * r0.y;
        acc[2] += nv[j] * r0.z; acc[3] += nv[j] * r0.w;
        acc[4] += nv[j] * r1.x; acc[5] += nv[j] * r1.y;
        acc[6] += nv[j] * r1.z; acc[7] += nv[j] * r1.w;
    }
    #pragma unroll
    for (int e = 0; e < 8; e++)
        #pragma unroll
        for (int o = 16; o; o >>= 1) acc[e] += __shfl_xor_sync(~0u, acc[e], o);
    if (lane == 0)
        #pragma unroll
        for (int e = 0; e < 8; e++) sl[wid][e] = acc[e];
    __syncthreads();
    if (tid < 8) {
        float L = 0.f;
        for (int w = 0; w < 8; w++) L += sl[w][tid];
        slog[tid] = L;
    }
    __syncthreads();
    if (tid == 0) {
        float p[8], mx = slog[0];
        for (int e = 1; e < 8; e++) mx = fmaxf(mx, slog[e]);
        float Z = 0.f;
        for (int e = 0; e < 8; e++) { p[e] = expf(slog[e] - mx); Z += p[e]; }
        float iZ = 1.0f / Z;
        for (int e = 0; e < 8; e++) p[e] *= iZ;
        int i1 = 0;
        for (int e = 1; e < 8; e++) if (p[e] > p[i1]) i1 = e;
        int i2 = (i1 == 0) ? 1 : 0;
        for (int e = 0; e < 8; e++) if (e != i1 && p[e] > p[i2]) i2 = e;
        float iw = 1.0f / (p[i1] + p[i2]);
        g_w2[2*t] = p[i1] * iw; g_w2[2*t+1] = p[i2] * iw;
        int p1 = atomicAdd(&g_cnt[i1], 1); g_list[i1 * Tn + p1] = t;
        int p2 = atomicAdd(&g_cnt[i2], 1); g_list[i2 * Tn + p2] = t;
        g_te[2*t] = i1; g_te[2*t+1] = i2;
        g_tp[2*t] = p1; g_tp[2*t+1] = p2;
    }
}

// ---- fp16 m16n8k16 GEMM: 64m x 128n, 4 warps, 2-stage, 4 CTAs/SM ---------
enum { M_UP = 0, M_S0, M_S1A, M_S1B, M_S2, M_DOWN };

template <int MODE>
__global__ __launch_bounds__(128, 4) void gemm16_kernel(const float* __restrict__ biasb)
{
    constexpr bool GATHER  = (MODE == M_UP);
    constexpr bool DO_GELU = (MODE == M_UP || MODE == M_S1A || MODE == M_S2);
    constexpr bool OUT_F32 = (MODE == M_DOWN);
    constexpr int  e0    = (MODE == M_S1A || MODE == M_S1B) ? 1 : (MODE == M_S2 ? 2 : 0);
    constexpr int  estep = (MODE == M_UP || MODE == M_DOWN) ? 1 : 4;
    constexpr int  Kd    = (MODE == M_UP) ? Hd : (MODE == M_S1B ? F2d : Fd);
    constexpr int  Nf    = (MODE == M_S1A) ? F2d : (MODE == M_DOWN ? Hd : Fd);
    constexpr int  KT    = Kd / 64;

    int z = blockIdx.z, e = e0 + estep * z;
    int M = g_cnt[e];
    int m0 = blockIdx.y * 64;
    if (m0 >= M) return;
    int n0 = blockIdx.x * 128;

    const __half* Wt =
        (MODE == M_UP)  ? g_upW16  : (MODE == M_S0)  ? g_s0W16  :
        (MODE == M_S1A) ? g_s1aW16 : (MODE == M_S1B) ? g_s1bW16 :
        (MODE == M_S2)  ? g_s2W16  : g_dnW16;

    const __half* A; void* Cv; int ldc;
    if constexpr (MODE == M_UP)       { A = g_nx;                   Cv = g_h1 + (size_t)e * SZF; ldc = Fd;  }
    else if constexpr (MODE == M_S0)  { A = g_h1 + (size_t)e * SZF; Cv = g_h2 + (size_t)e * SZF; ldc = Fd;  }
    else if constexpr (MODE == M_S1A) { A = g_h1 + (size_t)e * SZF; Cv = g_t1 + (size_t)z * SZT; ldc = F2d; }
    else if constexpr (MODE == M_S1B) { A = g_t1 + (size_t)z * SZT; Cv = g_h2 + (size_t)e * SZF; ldc = Fd;  }
    else if constexpr (MODE == M_S2)  { A = g_h1 + (size_t)e * SZF; Cv = g_h2 + (size_t)e * SZF; ldc = Fd;  }
    else { A = (((e & 3) == 3) ? g_h1 : g_h2) + (size_t)e * SZF;    Cv = g_dn + (size_t)e * SZD; ldc = Hd;  }

    const __half* Bp = Wt + (size_t)z * Kd * Nf + n0;   // [Kd][Nf] k-major
    const float*  bp = biasb + (size_t)z * Nf + n0;

    extern __shared__ uint32_t smem[];
    int* srow = (int*)(smem + STAGES * STW);
    int tid = threadIdx.x, lane = tid & 31, wid = tid >> 5;

    if (GATHER) {
        if (tid < 64) {
            int r = m0 + tid;
            srow[tid] = (r < M) ? g_list[e * Tn + r] : 0;
        }
        __syncthreads();
    }

    // A copy: m-row = (tid>>3)+16i (0..63), 16B chunk = word col (tid&7)*4
    int ar = tid >> 3;
    int ac = (tid & 7) * 4;            // words; halfs offset = ac*2
    // B copy: k-row = (tid>>4)+8i (0..63), word col (tid&15)*4 (0..60)
    int brw = tid >> 4;
    int bcl = (tid & 15) * 4;

    const __half* acur[4]; bool aval[4];
    #pragma unroll
    for (int i = 0; i < 4; i++) {
        int r = m0 + ar + 16 * i;
        aval[i] = (r < M);
        int src = GATHER ? (aval[i] ? srow[ar + 16 * i] : 0) : (aval[i] ? r : 0);
        acur[i] = A + (size_t)src * Kd + ac * 2;
    }
    const __half* bcur[8];
    #pragma unroll
    for (int i = 0; i < 8; i++)
        bcur[i] = Bp + (size_t)(brw + 8 * i) * Nf + bcl * 2;

    uint32_t sbase;
    { asm("{ .reg .u64 t; cvta.to.shared.u64 t, %1; cvt.u32.u64 %0, t; }"
          : "=r"(sbase) : "l"(smem)); }

    auto issue = [&](int kt) {
        if (kt < KT) {
            int st = kt & 1;
            uint32_t abase = sbase + (uint32_t)(st * STW) * 4;
            uint32_t bbase = abase + (uint32_t)ASTW * 4;
            int ko = kt * 64;   // halfs
            #pragma unroll
            for (int i = 0; i < 4; i++)
                cpa16(abase + (uint32_t)((ar + 16 * i) * 36 + ac) * 4, acur[i] + ko, aval[i]);
            #pragma unroll
            for (int i = 0; i < 8; i++)
                cpa16(bbase + (uint32_t)((brw + 8 * i) * 68 + bcl) * 4,
                      bcur[i] + (size_t)ko * Nf, true);
        }
        asm volatile("cp.async.commit_group;\n" ::: "memory");
    };
    issue(0); issue(1);

    int wm = wid & 1, wn = wid >> 1;   // 2x2 warps, warp tile 32m x 64n
    int qq = lane & 3, lg = lane >> 2;
    // B ldmatrix.trans lane addressing
    int krl = (lane & 7) + ((lane >> 3) & 1) * 8;
    int ncl = (lane >> 4) * 8;
    // A ldmatrix lane addressing: row = rm + (lane&15), kbyte = (lane>>4)*16
    uint32_t aoff[2];
    #pragma unroll
    for (int mi = 0; mi < 2; mi++) {
        int rm = wm * 32 + mi * 16 + (lane & 15);
        aoff[mi] = (uint32_t)rm * 144 + (uint32_t)(lane >> 4) * 16;
    }

    float acc[2][8][4];
    #pragma unroll
    for (int a = 0; a < 2; a++)
        #pragma unroll
        for (int b = 0; b < 8; b++)
            #pragma unroll
            for (int c = 0; c < 4; c++) acc[a][b][c] = 0.f;

    for (int kt = 0; kt < KT; kt++) {
        int st = kt & 1;
        asm volatile("cp.async.wait_group 1;\n" ::: "memory");
        __syncthreads();

        uint32_t Ab = sbase + (uint32_t)(st * STW) * 4;
        uint32_t Bb = Ab + (uint32_t)ASTW * 4;
        uint32_t bl = Bb + (uint32_t)krl * 272 + (uint32_t)(wn * 64 + ncl) * 2;
        #pragma unroll
        for (int kk = 0; kk < 4; kk++) {
            uint32_t af[2][4];
            #pragma unroll
            for (int mi = 0; mi < 2; mi++) {
                uint32_t addr = Ab + aoff[mi] + (uint32_t)(kk * 32);
                asm volatile(
                    "ldmatrix.sync.aligned.m8n8.x4.shared.b16 {%0,%1,%2,%3}, [%4];"
                    : "=r"(af[mi][0]), "=r"(af[mi][1]), "=r"(af[mi][2]), "=r"(af[mi][3])
                    : "r"(addr));
            }
            uint32_t bf[8][2];
            #pragma unroll
            for (int nj = 0; nj < 4; nj++) {
                uint32_t addr = bl + (uint32_t)(kk * 16) * 272 + (uint32_t)nj * 32;
                asm volatile(
                    "ldmatrix.sync.aligned.m8n8.x4.trans.shared.b16 {%0,%1,%2,%3}, [%4];"
                    : "=r"(bf[2*nj][0]), "=r"(bf[2*nj][1]),
                      "=r"(bf[2*nj+1][0]), "=r"(bf[2*nj+1][1])
                    : "r"(addr));
            }
            #pragma unroll
            for (int mi = 0; mi < 2; mi++)
                #pragma unroll
                for (int ni = 0; ni < 8; ni++)
                    asm volatile(
                        "mma.sync.aligned.m16n8k16.row.col.f32.f16.f16.f32 "
                        "{%0,%1,%2,%3}, {%4,%5,%6,%7}, {%8,%9}, {%0,%1,%2,%3};\n"
                        : "+f"(acc[mi][ni][0]), "+f"(acc[mi][ni][1]),
                          "+f"(acc[mi][ni][2]), "+f"(acc[mi][ni][3])
                        : "r"(af[mi][0]), "r"(af[mi][1]), "r"(af[mi][2]), "r"(af[mi][3]),
                          "r"(bf[ni][0]), "r"(bf[ni][1]));
        }
        __syncthreads();
        issue(kt + 2);
    }

    #pragma unroll
    for (int mi = 0; mi < 2; mi++) {
        #pragma unroll
        for (int hf = 0; hf < 2; hf++) {
            int r = m0 + wm * 32 + mi * 16 + lg + hf * 8;
            if (r < M) {
                #pragma unroll
                for (int ni = 0; ni < 8; ni++) {
                    int c = wn * 64 + ni * 8 + 2 * qq;
                    float v0 = acc[mi][ni][hf * 2 + 0] + bp[c];
                    float v1 = acc[mi][ni][hf * 2 + 1] + bp[c + 1];
                    if (DO_GELU) { v0 = gelu_f(v0); v1 = gelu_f(v1); }
                    if (OUT_F32) {
                        float* crow = (float*)Cv + (size_t)r * ldc + n0;
                        *reinterpret_cast<float2*>(crow + c) = make_float2(v0, v1);
                    } else {
                        __half* crow = (__half*)Cv + (size_t)r * ldc + n0;
                        *reinterpret_cast<__half2*>(crow + c) = __floats2half2_rn(v0, v1);
                    }
                }
            }
        }
    }
}

// ---------------- row LayerNorm over F on fp16 (optional gelu) ------------
template <bool DO_GELU>
__global__ __launch_bounds__(256, 1) void rowln16_kernel(
    int e0, const float* __restrict__ gg, const float* __restrict__ bb)
{
    int z = blockIdx.y, e = e0 + 4 * z;
    int row = blockIdx.x;
    if (row >= g_cnt[e]) return;
    __half* p = g_h2 + (size_t)e * SZF + (size_t)row * Fd;
    int tid = threadIdx.x, lane = tid & 31, wid = tid >> 5;
    __shared__ float ss[8], sq[8];
    uint4* p4 = reinterpret_cast<uint4*>(p);
    uint4 u[2];
    float vals[16];
    float s = 0.f, q = 0.f;
    #pragma unroll
    for (int i = 0; i < 2; i++) {
        u[i] = p4[tid + 256 * i];
        const __half2* h2 = reinterpret_cast<const __half2*>(&u[i]);
        #pragma unroll
        for (int j = 0; j < 4; j++) {
            float2 f = __half22float2(h2[j]);
            vals[i * 8 + 2 * j] = f.x; vals[i * 8 + 2 * j + 1] = f.y;
            s += f.x + f.y; q += f.x * f.x + f.y * f.y;
        }
    }
    #pragma unroll
    for (int o = 16; o; o >>= 1) { s += __shfl_xor_sync(~0u, s, o); q += __shfl_xor_sync(~0u, q, o); }
    if (lane == 0) { ss[wid] = s; sq[wid] = q; }
    __syncthreads();
    if (tid == 0) {
        float S = 0.f, Q = 0.f;
        for (int i = 0; i < 8; i++) { S += ss[i]; Q += sq[i]; }
        ss[0] = S; sq[0] = Q;
    }
    __syncthreads();
    float mean = ss[0] * (1.0f / Fd);
    float var = fmaxf(sq[0] * (1.0f / Fd) - mean * mean, 0.0f);
    float rs = rsqrtf(var + 1e-5f);
    const float* gr = gg + (size_t)z * Fd;
    const float* br = bb + (size_t)z * Fd;
    #pragma unroll
    for (int i = 0; i < 2; i++) {
        __half2 out[4];
        #pragma unroll
        for (int j = 0; j < 4; j++) {
            int idx = (tid + 256 * i) * 8 + 2 * j;
            float o0 = (vals[i * 8 + 2 * j]     - mean) * rs * gr[idx]     + br[idx];
            float o1 = (vals[i * 8 + 2 * j + 1] - mean) * rs * gr[idx + 1] + br[idx + 1];
            if (DO_GELU) { o0 = gelu_f(o0); o1 = gelu_f(o1); }
            out[j] = __floats2half2_rn(o0, o1);
        }
        p4[tid + 256 * i] = *reinterpret_cast<uint4*>(out);
    }
}

// ------------------------- combine epilogue -------------------------------
__global__ __launch_bounds__(256, 1) void combine_kernel(
    const float* __restrict__ x, float* __restrict__ y)
{
    int t = blockIdx.x, tid = threadIdx.x;
    int e1 = g_te[2*t], e2 = g_te[2*t+1];
    int p1 = g_tp[2*t], p2 = g_tp[2*t+1];
    float w1 = g_w2[2*t], w2 = g_w2[2*t+1];
    const float4* xv = reinterpret_cast<const float4*>(x + (size_t)t * Hd);
    const float4* d1 = reinterpret_cast<const float4*>(g_dn + (size_t)e1 * SZD + (size_t)p1 * Hd);
    const float4* d2 = reinterpret_cast<const float4*>(g_dn + (size_t)e2 * SZD + (size_t)p2 * Hd);
    float4 a = xv[tid], b = d1[tid], c = d2[tid], o;
    o.x = a.x + w1 * b.x + w2 * c.x;
    o.y = a.y + w1 * b.y + w2 * c.y;
    o.z = a.z + w1 * b.z + w2 * c.z;
    o.w = a.w + w1 * b.w + w2 * c.w;
    reinterpret_cast<float4*>(y + (size_t)t * Hd)[tid] = o;
}

// ---------------------------------------------------------------------------
extern "C" void kernel_launch(void* const* d_in, const int* in_sizes, int n_in,
                              void* d_out, int out_size)
{
    const float* x        = (const float*)d_in[0];
    const float* ln_g     = (const float*)d_in[1];
    const float* ln_b     = (const float*)d_in[2];
    const float* router_w = (const float*)d_in[3];
    const float* up_W     = (const float*)d_in[4];
    const float* up_b     = (const float*)d_in[5];
    const float* down_W   = (const float*)d_in[6];
    const float* down_b   = (const float*)d_in[7];
    const float* spec0_W  = (const float*)d_in[8];
    const float* spec0_b  = (const float*)d_in[9];
    const float* ln0_g    = (const float*)d_in[10];
    const float* ln0_b    = (const float*)d_in[11];
    const float* spec1a_W = (const float*)d_in[12];
    const float* spec1a_b = (const float*)d_in[13];
    const float* spec1b_W = (const float*)d_in[14];
    const float* spec1b_b = (const float*)d_in[15];
    const float* ln1_g    = (const float*)d_in[16];
    const float* ln1_b    = (const float*)d_in[17];
    const float* spec2_W  = (const float*)d_in[18];
    const float* spec2_b  = (const float*)d_in[19];
    float* y = (float*)d_out;

    static cudaStream_t s1 = nullptr, s2 = nullptr;
    static cudaEvent_t eRoot, eC0, eCall, eUP, eB;
    if (!s1) {
        cudaStreamCreateWithFlags(&s1, cudaStreamNonBlocking);
        cudaStreamCreateWithFlags(&s2, cudaStreamNonBlocking);
        cudaEventCreateWithFlags(&eRoot, cudaEventDisableTiming);
        cudaEventCreateWithFlags(&eC0,   cudaEventDisableTiming);
        cudaEventCreateWithFlags(&eCall, cudaEventDisableTiming);
        cudaEventCreateWithFlags(&eUP,   cudaEventDisableTiming);
        cudaEventCreateWithFlags(&eB,    cudaEventDisableTiming);
        cudaFuncSetAttribute((const void*)gemm16_kernel<M_UP>,   cudaFuncAttributeMaxDynamicSharedMemorySize, SMEM_BYTES);
        cudaFuncSetAttribute((const void*)gemm16_kernel<M_S0>,   cudaFuncAttributeMaxDynamicSharedMemorySize, SMEM_BYTES);
        cudaFuncSetAttribute((const void*)gemm16_kernel<M_S1A>,  cudaFuncAttributeMaxDynamicSharedMemorySize, SMEM_BYTES);
        cudaFuncSetAttribute((const void*)gemm16_kernel<M_S1B>,  cudaFuncAttributeMaxDynamicSharedMemorySize, SMEM_BYTES);
        cudaFuncSetAttribute((const void*)gemm16_kernel<M_S2>,   cudaFuncAttributeMaxDynamicSharedMemorySize, SMEM_BYTES);
        cudaFuncSetAttribute((const void*)gemm16_kernel<M_DOWN>, cudaFuncAttributeMaxDynamicSharedMemorySize, SMEM_BYTES);
    }

    // fork converts onto s1 (they depend only on harness inputs)
    cudaEventRecord(eRoot, 0);
    cudaStreamWaitEvent(s1, eRoot, 0);
    conv16_kernel<0><<<(int)((size_t)Ex * Hd * Fd / 2048), 256, 0, s1>>>(up_W);
    cudaEventRecord(eC0, s1);
    conv16_kernel<2><<<(int)((size_t)2 * Fd * Fd / 2048),  256, 0, s1>>>(spec0_W);
    conv16_kernel<3><<<(int)((size_t)2 * Fd * F2d / 2048), 256, 0, s1>>>(spec1a_W);
    conv16_kernel<5><<<(int)((size_t)2 * Fd * Fd / 2048),  256, 0, s1>>>(spec2_W);
    conv16_kernel<4><<<(int)((size_t)2 * F2d * Fd / 2048), 256, 0, s1>>>(spec1b_W);
    conv16_kernel<1><<<(int)((size_t)Ex * Fd * Hd / 2048), 256, 0, s1>>>(down_W);
    cudaEventRecord(eCall, s1);

    // default stream: router then UP (waits only on conv<0>)
    zero_cnt_kernel<<<1, 32>>>();
    ln_router_kernel<<<Tn, 256>>>(x, ln_g, ln_b, router_w);
    cudaStreamWaitEvent(0, eC0, 0);
    gemm16_kernel<M_UP><<<dim3(Fd/128, Tn/64, 8), 128, SMEM_BYTES>>>(up_b);
    cudaEventRecord(eUP, 0);

    // branch s2: S0 -> S2 -> rowln0 (experts 0,4 / 2,6)
    cudaStreamWaitEvent(s2, eUP, 0);
    cudaStreamWaitEvent(s2, eCall, 0);
    gemm16_kernel<M_S0><<<dim3(Fd/128, Tn/64, 2), 128, SMEM_BYTES, s2>>>(spec0_b);
    gemm16_kernel<M_S2><<<dim3(Fd/128, Tn/64, 2), 128, SMEM_BYTES, s2>>>(spec2_b);
    rowln16_kernel<true><<<dim3(Tn, 2), 256, 0, s2>>>(0, ln0_g, ln0_b);
    cudaEventRecord(eB, s2);

    // default branch: S1A -> S1B -> rowln1 (experts 1,5)
    cudaStreamWaitEvent(0, eCall, 0);
    gemm16_kernel<M_S1A><<<dim3(F2d/128, Tn/64, 2), 128, SMEM_BYTES>>>(spec1a_b);
    gemm16_kernel<M_S1B><<<dim3(Fd/128,  Tn/64, 2), 128, SMEM_BYTES>>>(spec1b_b);
    rowln16_kernel<false><<<dim3(Tn, 2), 256>>>(1, ln1_g, ln1_b);

    // join, then DOWN + combine
    cudaStreamWaitEvent(0, eB, 0);
    gemm16_kernel<M_DOWN><<<dim3(Hd/128, Tn/64, 8), 128, SMEM_BYTES>>>(down_b);
    combine_kernel<<<Tn, 256>>>(x, y);
}